// round 5
// baseline (speedup 1.0000x reference)
#include <cuda_runtime.h>
#include <cstdint>

// Problem constants
#define B_   8
#define N1_  8192
#define N2_  2048
#define K_   8
#define C1_  64
#define C2_  128
#define CIN_ 131   // C2 + 3
#define H_   128   // MLP widths
#define CAT_ 192   // H + C1

// Scratch for KNN indices (B*N1*K ints = 2 MB). Device global: allocation-free.
__device__ int g_knn[B_ * N1_ * K_];

// ---------------------------------------------------------------------------
// f32x2 helpers (Blackwell packed fp32; FFMA2 only reachable via PTX)
// ---------------------------------------------------------------------------
__device__ __forceinline__ unsigned long long ffma2(unsigned long long a,
                                                    unsigned long long b,
                                                    unsigned long long c) {
    unsigned long long d;
    asm("fma.rn.f32x2 %0, %1, %2, %3;" : "=l"(d) : "l"(a), "l"(b), "l"(c));
    return d;
}
__device__ __forceinline__ unsigned long long dup2(float v) {
    unsigned long long u;
    asm("mov.b64 %0, {%1, %1};" : "=l"(u) : "f"(v));
    return u;
}
__device__ __forceinline__ float2 u2f(unsigned long long u) {
    float2 v;
    asm("mov.b64 {%0, %1}, %2;" : "=f"(v.x), "=f"(v.y) : "l"(u));
    return v;
}

// ---------------------------------------------------------------------------
// Kernel 1: brute-force KNN (top-8 nearest xyz2 points per xyz1 point)
// One thread per query point; xyz2 for the batch staged in shared memory.
// All lanes scan candidates in lockstep -> smem reads are broadcasts.
// ---------------------------------------------------------------------------
__global__ __launch_bounds__(256) void knn_kernel(
    const float* __restrict__ xyz1,
    const float* __restrict__ xyz2) {
    __shared__ float sx[N2_], sy[N2_], sz[N2_];

    const int b = blockIdx.y;
    const int n = blockIdx.x * 256 + threadIdx.x;

    const float* p2 = xyz2 + (size_t)b * N2_ * 3;
    for (int j = threadIdx.x; j < N2_; j += 256) {
        sx[j] = p2[3 * j + 0];
        sy[j] = p2[3 * j + 1];
        sz[j] = p2[3 * j + 2];
    }
    __syncthreads();

    const int g = b * N1_ + n;
    const float qx = xyz1[3 * (size_t)g + 0];
    const float qy = xyz1[3 * (size_t)g + 1];
    const float qz = xyz1[3 * (size_t)g + 2];

    float bd[K_];
    int   bi[K_];
#pragma unroll
    for (int i = 0; i < K_; ++i) { bd[i] = 3.4e38f; bi[i] = 0; }

    for (int j = 0; j < N2_; ++j) {
        const float dx = sx[j] - qx;
        const float dy = sy[j] - qy;
        const float dz = sz[j] - qz;
        const float d = fmaf(dx, dx, fmaf(dy, dy, dz * dz));
        if (d < bd[K_ - 1]) {  // rare path: insert + bubble up (static indices)
            bd[K_ - 1] = d; bi[K_ - 1] = j;
#pragma unroll
            for (int s = K_ - 1; s > 0; --s) {
                if (bd[s] < bd[s - 1]) {
                    const float td = bd[s]; bd[s] = bd[s - 1]; bd[s - 1] = td;
                    const int   ti = bi[s]; bi[s] = bi[s - 1]; bi[s - 1] = ti;
                }
            }
        }
    }

#pragma unroll
    for (int i = 0; i < K_; ++i) g_knn[(size_t)g * K_ + i] = bi[i];
}

// ---------------------------------------------------------------------------
// Kernel 2: fused gather + MLP(131->128)+relu + MLP(128->128)+relu + maxpool(K)
//           + concat(feat1) + MLP(192->128)+relu
//
// Block = 128 threads handles 2 query points. Thread t: point pp = t>>6,
// channel pair c0 = 2*(t&63). Activations live in smem as DUPLICATED f32x2
// pairs so the inner loop is: 1 LDS.64 (broadcast) + 1 FFMA2 per 2 MACs,
// with each weight LDG.64 reused across 8 neighbor rows.
// ---------------------------------------------------------------------------
__global__ __launch_bounds__(128) void fused_mlp_kernel(
    const float* __restrict__ xyz1,
    const float* __restrict__ xyz2,
    const float* __restrict__ feat1,
    const float* __restrict__ feat2,
    const float* __restrict__ W0, const float* __restrict__ b0,
    const float* __restrict__ W1, const float* __restrict__ b1,
    const float* __restrict__ W2, const float* __restrict__ b2,
    float* __restrict__ out) {

    __shared__ unsigned long long a2[2][K_][CIN_ + 1];  // gathered input rows
    __shared__ unsigned long long h2[2][K_][H_];        // hidden after GEMM1
    __shared__ unsigned long long cat2[2][CAT_];        // [pooled(128) | feat1(64)]

    const int t = threadIdx.x;
    const int pid = blockIdx.x;

    // ---- gather phase: both points, all threads ----
#pragma unroll
    for (int pp = 0; pp < 2; ++pp) {
        const int g = pid * 2 + pp;
        const int b = g >> 13;  // N1 = 8192
#pragma unroll
        for (int r = 0; r < K_; ++r) {
            const int j = g_knn[(size_t)g * K_ + r];   // uniform across block
            const float* f2row = feat2 + ((size_t)(b * N2_ + j)) * C2_;
            a2[pp][r][t] = dup2(f2row[t]);             // t in [0,128): coalesced
            if (t < 3) {
                const float d = xyz2[((size_t)(b * N2_ + j)) * 3 + t]
                              - xyz1[(size_t)g * 3 + t];
                a2[pp][r][C2_ + t] = dup2(d);
            }
        }
        if (t < C1_) cat2[pp][H_ + t] = dup2(feat1[(size_t)g * C1_ + t]);
    }
    __syncthreads();

    const int pp = t >> 6;        // which of the 2 points
    const int cp = t & 63;        // channel-pair index: channels 2cp, 2cp+1

    const unsigned long long* W0u = (const unsigned long long*)W0;
    const unsigned long long* W1u = (const unsigned long long*)W1;
    const unsigned long long* W2u = (const unsigned long long*)W2;

    unsigned long long acc[K_];

    // ---- GEMM1: (8 x 131) @ (131 x 128), relu ----
    {
        const unsigned long long bias = ((const unsigned long long*)b0)[cp];
#pragma unroll
        for (int r = 0; r < K_; ++r) acc[r] = bias;
#pragma unroll 4
        for (int k = 0; k < CIN_; ++k) {
            const unsigned long long w = W0u[k * 64 + cp];
#pragma unroll
            for (int r = 0; r < K_; ++r)
                acc[r] = ffma2(a2[pp][r][k], w, acc[r]);
        }
#pragma unroll
        for (int r = 0; r < K_; ++r) {
            float2 v = u2f(acc[r]);
            h2[pp][r][2 * cp]     = dup2(fmaxf(v.x, 0.0f));
            h2[pp][r][2 * cp + 1] = dup2(fmaxf(v.y, 0.0f));
        }
    }
    __syncthreads();

    // ---- GEMM2: (8 x 128) @ (128 x 128), relu + max over K ----
    {
        const unsigned long long bias = ((const unsigned long long*)b1)[cp];
#pragma unroll
        for (int r = 0; r < K_; ++r) acc[r] = bias;
#pragma unroll 4
        for (int k = 0; k < H_; ++k) {
            const unsigned long long w = W1u[k * 64 + cp];
#pragma unroll
            for (int r = 0; r < K_; ++r)
                acc[r] = ffma2(h2[pp][r][k], w, acc[r]);
        }
        // max_r relu(x_r) == max(0, max_r x_r)
        float px = 0.0f, py = 0.0f;
#pragma unroll
        for (int r = 0; r < K_; ++r) {
            float2 v = u2f(acc[r]);
            px = fmaxf(px, v.x);
            py = fmaxf(py, v.y);
        }
        cat2[pp][2 * cp]     = dup2(px);
        cat2[pp][2 * cp + 1] = dup2(py);
    }
    __syncthreads();

    // ---- GEMM3: (1 x 192) @ (192 x 128), relu ----
    {
        unsigned long long acc3 = ((const unsigned long long*)b2)[cp];
#pragma unroll 4
        for (int k = 0; k < CAT_; ++k)
            acc3 = ffma2(cat2[pp][k], W2u[k * 64 + cp], acc3);

        float2 v = u2f(acc3);
        v.x = fmaxf(v.x, 0.0f);
        v.y = fmaxf(v.y, 0.0f);
        const int g = pid * 2 + pp;
        *(float2*)(out + (size_t)g * H_ + 2 * cp) = v;
    }
}

// ---------------------------------------------------------------------------
// Launch
// ---------------------------------------------------------------------------
extern "C" void kernel_launch(void* const* d_in, const int* in_sizes, int n_in,
                              void* d_out, int out_size) {
    const float* xyz1  = (const float*)d_in[0];
    const float* xyz2  = (const float*)d_in[1];
    const float* feat1 = (const float*)d_in[2];
    const float* feat2 = (const float*)d_in[3];
    const float* W0    = (const float*)d_in[4];
    const float* b0    = (const float*)d_in[5];
    const float* W1    = (const float*)d_in[6];
    const float* b1    = (const float*)d_in[7];
    const float* W2    = (const float*)d_in[8];
    const float* b2    = (const float*)d_in[9];
    float* out = (float*)d_out;

    knn_kernel<<<dim3(N1_ / 256, B_), 256>>>(xyz1, xyz2);

    fused_mlp_kernel<<<(B_ * N1_) / 2, 128>>>(
        xyz1, xyz2, feat1, feat2, W0, b0, W1, b1, W2, b2, out);
}

// round 6
// speedup vs baseline: 2.5109x; 2.5109x over previous
#include <cuda_runtime.h>
#include <cstdint>

// Problem constants
#define B_   8
#define N1_  8192
#define N2_  2048
#define K_   8
#define C1_  64
#define C2_  128
#define H_   128
#define CAT_ 192   // H + C1

// Device-global scratch (allocation-free)
__device__ int   g_knn[B_ * N1_ * K_];                 // 2 MB
__device__ float g_P[B_ * N2_ * H_];                   // 8 MB: feat2 @ W0[:128] + b0
__device__ float g_cat[B_ * N1_ * CAT_];               // 50 MB: [pooled | feat1]

// ---------------------------------------------------------------------------
// f32x2 helpers
// ---------------------------------------------------------------------------
__device__ __forceinline__ unsigned long long ffma2(unsigned long long a,
                                                    unsigned long long b,
                                                    unsigned long long c) {
    unsigned long long d;
    asm("fma.rn.f32x2 %0, %1, %2, %3;" : "=l"(d) : "l"(a), "l"(b), "l"(c));
    return d;
}
__device__ __forceinline__ unsigned long long dup2(float v) {
    unsigned long long u;
    asm("mov.b64 %0, {%1, %1};" : "=l"(u) : "f"(v));
    return u;
}
__device__ __forceinline__ unsigned long long pack2(float x, float y) {
    unsigned long long u;  // lo = x, hi = y
    asm("mov.b64 %0, {%1, %2};" : "=l"(u) : "f"(x), "f"(y));
    return u;
}
__device__ __forceinline__ float2 u2f(unsigned long long u) {
    float2 v;
    asm("mov.b64 {%0, %1}, %2;" : "=f"(v.x), "=f"(v.y) : "l"(u));
    return v;
}

// ---------------------------------------------------------------------------
// Kernel 1: brute-force KNN (unchanged from passing R4 version)
// ---------------------------------------------------------------------------
__global__ __launch_bounds__(256) void knn_kernel(
    const float* __restrict__ xyz1,
    const float* __restrict__ xyz2) {
    __shared__ float sx[N2_], sy[N2_], sz[N2_];

    const int b = blockIdx.y;
    const int n = blockIdx.x * 256 + threadIdx.x;

    const float* p2 = xyz2 + (size_t)b * N2_ * 3;
    for (int j = threadIdx.x; j < N2_; j += 256) {
        sx[j] = p2[3 * j + 0];
        sy[j] = p2[3 * j + 1];
        sz[j] = p2[3 * j + 2];
    }
    __syncthreads();

    const int g = b * N1_ + n;
    const float qx = xyz1[3 * (size_t)g + 0];
    const float qy = xyz1[3 * (size_t)g + 1];
    const float qz = xyz1[3 * (size_t)g + 2];

    float bd[K_];
    int   bi[K_];
#pragma unroll
    for (int i = 0; i < K_; ++i) { bd[i] = 3.4e38f; bi[i] = 0; }

    for (int j = 0; j < N2_; ++j) {
        const float dx = sx[j] - qx;
        const float dy = sy[j] - qy;
        const float dz = sz[j] - qz;
        const float d = fmaf(dx, dx, fmaf(dy, dy, dz * dz));
        if (d < bd[K_ - 1]) {
            bd[K_ - 1] = d; bi[K_ - 1] = j;
#pragma unroll
            for (int s = K_ - 1; s > 0; --s) {
                if (bd[s] < bd[s - 1]) {
                    const float td = bd[s]; bd[s] = bd[s - 1]; bd[s - 1] = td;
                    const int   ti = bi[s]; bi[s] = bi[s - 1]; bi[s - 1] = ti;
                }
            }
        }
    }
#pragma unroll
    for (int i = 0; i < K_; ++i) g_knn[(size_t)g * K_ + i] = bi[i];
}

// ---------------------------------------------------------------------------
// Kernel 2: P = feat2 @ W0[:128,:] + b0   (gather-invariant GEMM1 part)
// Block = 128 threads, 8 feat2 rows. Thread t = output column; 4 row-pair
// accumulators; activations broadcast from smem as adjacent row pairs.
// ---------------------------------------------------------------------------
__global__ __launch_bounds__(128) void precompute_p_kernel(
    const float* __restrict__ feat2,
    const float* __restrict__ W0,
    const float* __restrict__ b0) {
    __shared__ float s_f[C2_ * 10];  // [k][10] (8 rows + pad, 8B-aligned pairs)

    const int t = threadIdx.x;
    const int base = blockIdx.x * 8;  // row in [0, B*N2)

    for (int idx = t; idx < 8 * C2_; idx += 128) {
        const int r = idx >> 7, k = idx & 127;
        s_f[k * 10 + r] = feat2[(size_t)(base + r) * C2_ + k];
    }
    __syncthreads();

    unsigned long long acc[4];
    const unsigned long long bb = dup2(b0[t]);
#pragma unroll
    for (int rp = 0; rp < 4; ++rp) acc[rp] = bb;

#pragma unroll 4
    for (int k = 0; k < C2_; ++k) {
        const unsigned long long wd = dup2(W0[k * H_ + t]);
#pragma unroll
        for (int rp = 0; rp < 4; ++rp) {
            const unsigned long long a =
                *(const unsigned long long*)&s_f[k * 10 + 2 * rp];
            acc[rp] = ffma2(a, wd, acc[rp]);
        }
    }
#pragma unroll
    for (int rp = 0; rp < 4; ++rp) {
        const float2 v = u2f(acc[rp]);
        g_P[(size_t)(base + 2 * rp) * H_ + t]     = v.x;
        g_P[(size_t)(base + 2 * rp + 1) * H_ + t] = v.y;
    }
}

// ---------------------------------------------------------------------------
// Kernel 3: fused gather+xyz MLP1-finish + GEMM2 + relu + maxpool + concat.
// One warp per query point, 8 points per 256-thread block.
// GEMM2 inner loop per k per warp: 2 LDS.128 + 4 LDG.32 + 4 dup + 16 FFMA2
//  -> ~6 L1 wavefronts per 32 FMA-pipe cycles (FMA-bound by design).
// ---------------------------------------------------------------------------
__global__ __launch_bounds__(256) void fused_kernel(
    const float* __restrict__ xyz1,
    const float* __restrict__ xyz2,
    const float* __restrict__ feat1,
    const float* __restrict__ W0,
    const float* __restrict__ W1,
    const float* __restrict__ b1) {
    __shared__ unsigned long long h_s[8][H_][4];  // [warp][k][row-pair]

    const int w    = threadIdx.x >> 5;
    const int lane = threadIdx.x & 31;
    const int g    = blockIdx.x * 8 + w;
    const int b    = g >> 13;  // N1 = 8192

    // ---- finish GEMM1: h = relu(P[j] + xyz_diff @ W0[128:131,:]) ----
    {
        const int rp = lane & 3, cg = lane >> 2;
        const int r0 = 2 * rp, r1 = r0 + 1;
        const int j0 = g_knn[(size_t)g * K_ + r0];
        const int j1 = g_knn[(size_t)g * K_ + r1];
        const float qx = xyz1[(size_t)g * 3 + 0];
        const float qy = xyz1[(size_t)g * 3 + 1];
        const float qz = xyz1[(size_t)g * 3 + 2];
        const float* p0 = xyz2 + (size_t)(b * N2_ + j0) * 3;
        const float* p1 = xyz2 + (size_t)(b * N2_ + j1) * 3;
        const float d00 = p0[0] - qx, d01 = p0[1] - qy, d02 = p0[2] - qz;
        const float d10 = p1[0] - qx, d11 = p1[1] - qy, d12 = p1[2] - qz;
        const float* P0 = g_P + (size_t)(b * N2_ + j0) * H_;
        const float* P1 = g_P + (size_t)(b * N2_ + j1) * H_;
#pragma unroll
        for (int i = 0; i < 16; ++i) {
            const int c = cg + 8 * i;
            const float v0 = W0[128 * H_ + c];
            const float v1 = W0[129 * H_ + c];
            const float v2 = W0[130 * H_ + c];
            float h0 = __ldcs(P0 + c);
            float h1 = __ldcs(P1 + c);
            h0 = fmaf(d02, v2, fmaf(d01, v1, fmaf(d00, v0, h0)));
            h1 = fmaf(d12, v2, fmaf(d11, v1, fmaf(d10, v0, h1)));
            h_s[w][c][rp] = pack2(fmaxf(h0, 0.0f), fmaxf(h1, 0.0f));
        }
    }
    __syncwarp();

    // ---- GEMM2: (8 x 128) @ (128 x 128); rows packed in f32x2 pairs ----
    unsigned long long acc[4][4];  // [row-pair][col i], col = lane + 32*i
#pragma unroll
    for (int i = 0; i < 4; ++i) {
        const unsigned long long bb = dup2(b1[lane + 32 * i]);
#pragma unroll
        for (int r = 0; r < 4; ++r) acc[r][i] = bb;
    }
#pragma unroll 2
    for (int k = 0; k < H_; ++k) {
        const ulonglong2 hv01 = *(const ulonglong2*)&h_s[w][k][0];
        const ulonglong2 hv23 = *(const ulonglong2*)&h_s[w][k][2];
        const unsigned long long hv[4] = {hv01.x, hv01.y, hv23.x, hv23.y};
#pragma unroll
        for (int i = 0; i < 4; ++i) {
            const unsigned long long wd = dup2(W1[k * H_ + lane + 32 * i]);
#pragma unroll
            for (int r = 0; r < 4; ++r) acc[r][i] = ffma2(hv[r], wd, acc[r][i]);
        }
    }

    // ---- relu + maxpool over 8 neighbors; write [pooled | feat1] ----
    float* catg = g_cat + (size_t)g * CAT_;
#pragma unroll
    for (int i = 0; i < 4; ++i) {
        float m = 0.0f;  // max_r relu(x) == max(0, max_r x)
#pragma unroll
        for (int r = 0; r < 4; ++r) {
            const float2 v = u2f(acc[r][i]);
            m = fmaxf(m, fmaxf(v.x, v.y));
        }
        catg[lane + 32 * i] = m;
    }
    catg[H_ + lane]      = feat1[(size_t)g * C1_ + lane];
    catg[H_ + 32 + lane] = feat1[(size_t)g * C1_ + 32 + lane];
}

// ---------------------------------------------------------------------------
// Kernel 4: GEMM3  out = relu(cat @ W2 + b2), cat = (BN1 x 192).
// Block = 256 threads, 32 points. Thread: 4 points (2 row-pairs) x 4 cols.
// ---------------------------------------------------------------------------
__global__ __launch_bounds__(256) void gemm3_kernel(
    const float* __restrict__ W2,
    const float* __restrict__ b2,
    float* __restrict__ out) {
    __shared__ float cat_s[CAT_ * 34];  // [k][34]: 32 points + pad (136B rows)

    const int t = threadIdx.x;
    const int base = blockIdx.x * 32;

    for (int idx = t; idx < 32 * CAT_; idx += 256) {
        const int p = idx / CAT_;
        const int k = idx - p * CAT_;
        cat_s[k * 34 + p] = __ldcs(&g_cat[(size_t)(base + p) * CAT_ + k]);
    }
    __syncthreads();

    const int q  = t & 7;   // point-quad: points 4q .. 4q+3
    const int cg = t >> 3;  // cols: cg + 32*i

    unsigned long long acc[2][4];
#pragma unroll
    for (int i = 0; i < 4; ++i) {
        const unsigned long long bb = dup2(b2[cg + 32 * i]);
        acc[0][i] = bb;
        acc[1][i] = bb;
    }

#pragma unroll 2
    for (int k = 0; k < CAT_; ++k) {
        const unsigned long long a0 =
            *(const unsigned long long*)&cat_s[k * 34 + 4 * q];
        const unsigned long long a1 =
            *(const unsigned long long*)&cat_s[k * 34 + 4 * q + 2];
#pragma unroll
        for (int i = 0; i < 4; ++i) {
            const unsigned long long wd = dup2(W2[k * H_ + cg + 32 * i]);
            acc[0][i] = ffma2(a0, wd, acc[0][i]);
            acc[1][i] = ffma2(a1, wd, acc[1][i]);
        }
    }

#pragma unroll
    for (int pr = 0; pr < 2; ++pr) {
#pragma unroll
        for (int i = 0; i < 4; ++i) {
            const float2 v = u2f(acc[pr][i]);
            const int c = cg + 32 * i;
            out[(size_t)(base + 4 * q + 2 * pr)     * H_ + c] = fmaxf(v.x, 0.0f);
            out[(size_t)(base + 4 * q + 2 * pr + 1) * H_ + c] = fmaxf(v.y, 0.0f);
        }
    }
}

// ---------------------------------------------------------------------------
// Launch
// ---------------------------------------------------------------------------
extern "C" void kernel_launch(void* const* d_in, const int* in_sizes, int n_in,
                              void* d_out, int out_size) {
    const float* xyz1  = (const float*)d_in[0];
    const float* xyz2  = (const float*)d_in[1];
    const float* feat1 = (const float*)d_in[2];
    const float* feat2 = (const float*)d_in[3];
    const float* W0    = (const float*)d_in[4];
    const float* b0    = (const float*)d_in[5];
    const float* W1    = (const float*)d_in[6];
    const float* b1    = (const float*)d_in[7];
    const float* W2    = (const float*)d_in[8];
    const float* b2    = (const float*)d_in[9];
    float* out = (float*)d_out;

    precompute_p_kernel<<<(B_ * N2_) / 8, 128>>>(feat2, W0, b0);
    knn_kernel<<<dim3(N1_ / 256, B_), 256>>>(xyz1, xyz2);
    fused_kernel<<<(B_ * N1_) / 8, 256>>>(xyz1, xyz2, feat1, W0, W1, b1);
    gemm3_kernel<<<(B_ * N1_) / 32, 256>>>(W2, b2, out);
}